// round 16
// baseline (speedup 1.0000x reference)
#include <cuda_runtime.h>
#include <cuda_bf16.h>
#include <cstdint>

#define PP        4096
#define HH        256
#define NSTEPS    100
#define DTC       0.1f
#define SQRT_DTC  0.31622776601683794f
#define M_CTA     32
#define NCTA      (PP / M_CTA)   // 128
#define NTHREADS  512            // 16 warps = 8 n-groups x 2 k-groups
#define AS        264            // bf16 row stride (528B): conflict-free ldsm/STS

// smem: 4 act bufs (67584) + w0 (8192) + b0/b1/b2 (3072) + b3 (32) + st (256)
//       + inp0 (1024) + pf (32768) + pf3 (8192) = 121120
#define SMEM_BYTES 121120

// Weight fragments, mma.m16n8k16 B-op order, hi+lo packed per uint4:
// [kt][n8][lane] -> {bh0, bh1, bl0, bl1}
__device__ uint4 g_W1[16 * 32 * 32];
__device__ uint4 g_W2[16 * 32 * 32];
__device__ uint4 g_W3[16 * 32];

__device__ __forceinline__ float softplusf(float x) {
    return fmaxf(x, 0.0f) + log1pf(expf(-fabsf(x)));
}
__device__ __forceinline__ uint32_t bfpack(float a, float b) {
    __nv_bfloat162 v = __floats2bfloat162_rn(a, b);   // .x = a (low half)
    return *reinterpret_cast<uint32_t*>(&v);
}

// ---------------- prep: fp32 weights -> hi/lo bf16 fragment arrays ----------------
__global__ void prep_kernel(const float* __restrict__ W1,
                            const float* __restrict__ W2,
                            const float* __restrict__ W3) {
    const int idx = blockIdx.x * blockDim.x + threadIdx.x;
    const int TOT = 16 * 32 * 32;
    if (idx < 2 * TOT) {
        const int l = idx / TOT, r = idx % TOT;
        const int kt = r >> 10;
        const int n8 = (r >> 5) & 31;
        const int lane = r & 31;
        const int k0 = kt * 16 + (lane & 3) * 2;
        const int n = n8 * 8 + (lane >> 2);
        const float* W = l ? W2 : W1;
        float x[4];
        x[0] = W[(k0)     * HH + n];
        x[1] = W[(k0 + 1) * HH + n];
        x[2] = W[(k0 + 8) * HH + n];
        x[3] = W[(k0 + 9) * HH + n];
        float h[4], lo[4];
#pragma unroll
        for (int i = 0; i < 4; i++) {
            h[i]  = __bfloat162float(__float2bfloat16(x[i]));
            lo[i] = x[i] - h[i];
        }
        uint4 v;
        v.x = bfpack(h[0], h[1]);   v.y = bfpack(h[2], h[3]);
        v.z = bfpack(lo[0], lo[1]); v.w = bfpack(lo[2], lo[3]);
        if (l) g_W2[r] = v; else g_W1[r] = v;
    } else if (idx < 2 * TOT + 512) {
        const int r = idx - 2 * TOT;
        const int kt = r >> 5, lane = r & 31;
        const int k0 = kt * 16 + (lane & 3) * 2;
        const int n = lane >> 2;
        float x[4] = {0.f, 0.f, 0.f, 0.f};
        if (n < 5) {
            x[0] = W3[(k0)     * 5 + n];
            x[1] = W3[(k0 + 1) * 5 + n];
            x[2] = W3[(k0 + 8) * 5 + n];
            x[3] = W3[(k0 + 9) * 5 + n];
        }
        float h[4], lo[4];
#pragma unroll
        for (int i = 0; i < 4; i++) {
            h[i]  = __bfloat162float(__float2bfloat16(x[i]));
            lo[i] = x[i] - h[i];
        }
        uint4 v;
        v.x = bfpack(h[0], h[1]);   v.y = bfpack(h[2], h[3]);
        v.z = bfpack(lo[0], lo[1]); v.w = bfpack(lo[2], lo[3]);
        g_W3[r] = v;
    }
}

// ---------------- tensor-core primitives ----------------
__device__ __forceinline__ void ldsm4(uint32_t* r, const __nv_bfloat16* p) {
    uint32_t addr = (uint32_t)__cvta_generic_to_shared(p);
    asm volatile("ldmatrix.sync.aligned.m8n8.x4.shared.b16 {%0,%1,%2,%3}, [%4];"
                 : "=r"(r[0]), "=r"(r[1]), "=r"(r[2]), "=r"(r[3]) : "r"(addr));
}
__device__ __forceinline__ void mma_bf16(float* d, const uint32_t* a,
                                         uint32_t b0, uint32_t b1) {
    asm volatile(
        "mma.sync.aligned.m16n8k16.row.col.f32.bf16.bf16.f32 "
        "{%0,%1,%2,%3}, {%4,%5,%6,%7}, {%8,%9}, {%0,%1,%2,%3};"
        : "+f"(d[0]), "+f"(d[1]), "+f"(d[2]), "+f"(d[3])
        : "r"(a[0]), "r"(a[1]), "r"(a[2]), "r"(a[3]), "r"(b0), "r"(b1));
}

struct AFrag  { uint32_t ah0[4], ah1[4], al0[4], al1[4]; };
struct BFrag4 { uint4 b[4]; };   // 4 n-tiles: hi in (x,y), lo in (z,w)

__device__ __forceinline__ void load_A(AFrag& a, const __nv_bfloat16* Ah,
                                       const __nv_bfloat16* Al, int arow, int co) {
    ldsm4(a.ah0, Ah + arow * AS + co);
    ldsm4(a.ah1, Ah + (arow + 16) * AS + co);
    ldsm4(a.al0, Al + arow * AS + co);
    ldsm4(a.al1, Al + (arow + 16) * AS + co);
}
__device__ __forceinline__ void load_B4(BFrag4& f, const uint4* __restrict__ bp,
                                        int kt) {
    const uint4* p = bp + kt * 1024;
#pragma unroll
    for (int nt = 0; nt < 4; nt++) f.b[nt] = __ldg(p + nt * 32);
}
__device__ __forceinline__ void mma24(float D[2][4][4], const AFrag& a,
                                      const BFrag4& f) {
#pragma unroll
    for (int nt = 0; nt < 4; nt++) {
        mma_bf16(D[0][nt], a.ah0, f.b[nt].x, f.b[nt].y);
        mma_bf16(D[1][nt], a.ah1, f.b[nt].x, f.b[nt].y);
        mma_bf16(D[0][nt], a.ah0, f.b[nt].z, f.b[nt].w);
        mma_bf16(D[1][nt], a.ah1, f.b[nt].z, f.b[nt].w);
        mma_bf16(D[0][nt], a.al0, f.b[nt].x, f.b[nt].y);
        mma_bf16(D[1][nt], a.al1, f.b[nt].x, f.b[nt].y);
    }
}

// Split-K mainloop: warp (wn,kg) computes 2 m-tiles x 4 n-tiles over kt in
// [8kg, 8kg+8). A single-buffered (smem), B double-buffered (L2).
__device__ __forceinline__ void tc_gemm_sk(
    float D[2][4][4], const __nv_bfloat16* Ah, const __nv_bfloat16* Al,
    const uint4* __restrict__ B, int wn, int kg, int lane) {
#pragma unroll
    for (int mt = 0; mt < 2; mt++)
#pragma unroll
        for (int nt = 0; nt < 4; nt++)
#pragma unroll
            for (int i = 0; i < 4; i++) D[mt][nt][i] = 0.0f;

    const int arow = (lane & 7) + ((lane >> 3) & 1) * 8;
    const int acol = (lane >> 4) * 8;
    const int kt0 = 8 * kg;
    const uint4* bp = B + 4 * wn * 32 + lane;   // + kt*1024 per tile

    BFrag4 B0, B1;
    AFrag A;
    load_B4(B0, bp, kt0);
    load_B4(B1, bp, kt0 + 1);
#pragma unroll
    for (int i = 0; i < 4; i++) {
        const int kt = kt0 + 2 * i;
        load_A(A, Ah, Al, arow, kt * 16 + acol);
        mma24(D, A, B0);
        if (i < 3) load_B4(B0, bp, kt + 2);
        load_A(A, Ah, Al, arow, (kt + 1) * 16 + acol);
        mma24(D, A, B1);
        if (i < 3) load_B4(B1, bp, kt + 3);
    }
}

// Cross-kg partial exchange: warp stores m-tile (1-kg), keeps kg.
// pf slot (wn*2 + mt): one writer (kg = 1-mt), one reader (kg = mt).
__device__ __forceinline__ void exchange_partial(
    float D[2][4][4], float4* pf, int wn, int kg, int lane, float v[4][4]) {
    const int mtw = 1 - kg;
#pragma unroll
    for (int nt = 0; nt < 4; nt++)
        pf[(wn * 2 + mtw) * 128 + nt * 32 + lane] =
            make_float4(D[mtw][nt][0], D[mtw][nt][1], D[mtw][nt][2], D[mtw][nt][3]);
    __syncthreads();
#pragma unroll
    for (int nt = 0; nt < 4; nt++) {
        float4 pv = pf[(wn * 2 + kg) * 128 + nt * 32 + lane];
        v[nt][0] = D[kg][nt][0] + pv.x;
        v[nt][1] = D[kg][nt][1] + pv.y;
        v[nt][2] = D[kg][nt][2] + pv.z;
        v[nt][3] = D[kg][nt][3] + pv.w;
    }
}

// ---------------- main persistent kernel ----------------
__global__ void __launch_bounds__(NTHREADS, 1) lv_tc_kernel(
    const float* __restrict__ W0, const float* __restrict__ b0,
    const float* __restrict__ b1, const float* __restrict__ b2,
    const float* __restrict__ b3,
    const float* __restrict__ obs_init, const float* __restrict__ feature_init,
    const float* __restrict__ tn_store, const float* __restrict__ x1_store,
    const float* __restrict__ x2_store, const float* __restrict__ path_seed,
    float* __restrict__ out) {
    extern __shared__ __align__(16) unsigned char smem_raw[];
    __nv_bfloat16* Ah = reinterpret_cast<__nv_bfloat16*>(smem_raw);
    __nv_bfloat16* Al = Ah + M_CTA * AS;
    __nv_bfloat16* Bh = Al + M_CTA * AS;
    __nv_bfloat16* Bl = Bh + M_CTA * AS;
    float* w0_sh = reinterpret_cast<float*>(Bl + M_CTA * AS);
    float* b0_sh = w0_sh + 8 * HH;
    float* b1_sh = b0_sh + HH;
    float* b2_sh = b1_sh + HH;
    float* b3_sh = b2_sh + HH;       // 8
    float* st_sh = b3_sh + 8;        // 64
    float* inp0  = st_sh + 64;       // 32*8
    float4* pf   = reinterpret_cast<float4*>(inp0 + M_CTA * 8);  // 2048 f4 = 32KB
    float* pf3   = reinterpret_cast<float*>(pf + 2048);          // 2048 f = 8KB

    const int tid = threadIdx.x;
    const int warp = tid >> 5, lane = tid & 31;
    const int wn = warp & 7, kg = warp >> 3;
    const int row0 = blockIdx.x * M_CTA;

    // one-time staging
    for (int i = tid; i < 8 * HH; i += NTHREADS) w0_sh[i] = W0[i];
    if (tid < HH) { b0_sh[tid] = b0[tid]; b1_sh[tid] = b1[tid]; b2_sh[tid] = b2[tid]; }
    if (tid < 8) b3_sh[tid] = (tid < 5) ? b3[tid] : 0.0f;
    if (tid < M_CTA * 2) st_sh[tid] = obs_init[row0 * 2 + tid];
    if (tid < M_CTA * 8) {
        int r = tid >> 3, k = tid & 7;
        inp0[tid] = (k < 2) ? obs_init[(row0 + r) * 2 + k]
                            : feature_init[(row0 + r) * 6 + (k - 2)];
    }
    // layer-3 B fragments for this warp's two k-slices (constant -> registers)
    const uint4 w3v0 = __ldg(&g_W3[(2 * wn)     * 32 + lane]);
    const uint4 w3v1 = __ldg(&g_W3[(2 * wn + 1) * 32 + lane]);
    float t_reg = __ldg(feature_init);   // t0 = feature_init[0,0,0]
    __syncthreads();

    // layer-0 mapping: 512 threads -> col n = tid&255, row half rh = tid>>8
    const int l0n  = tid & 255;
    const int l0r0 = (tid >> 8) * 16;    // rows [l0r0, l0r0+16)
    const int rbase = lane >> 2;

#pragma unroll 1
    for (int s = 0; s < NSTEPS; s++) {
        // ---- layer 0 (scalar fp32) -> Ah/Al
        {
            const int n = l0n;
            if (s == 0) {
#pragma unroll 4
                for (int rr = 0; rr < 16; rr++) {
                    const int r = l0r0 + rr;
                    float a = b0_sh[n];
#pragma unroll
                    for (int k = 0; k < 8; k++)
                        a = fmaf(inp0[r * 8 + k], w0_sh[k * HH + n], a);
                    a = fmaxf(a, 0.0f);
                    float h = __bfloat162float(__float2bfloat16(a));
                    Ah[r * AS + n] = __float2bfloat16(a);
                    Al[r * AS + n] = __float2bfloat16(a - h);
                }
            } else {
                t_reg += DTC;   // exact sequential fp32 time accumulation
                const int i = s - 1;
                const float f_tn = __ldg(tn_store + i);
                const float f_x1 = __ldg(x1_store + i);
                const float f_x2 = __ldg(x2_store + i);
                float base = b0_sh[n];
                base = fmaf(t_reg, w0_sh[2 * HH + n], base);
                base = fmaf(f_tn,  w0_sh[3 * HH + n], base);
                base = fmaf(f_x1,  w0_sh[4 * HH + n], base);
                base = fmaf(f_x2,  w0_sh[5 * HH + n], base);
                base = fmaf(f_x1,  w0_sh[6 * HH + n], base);
                base = fmaf(f_x2,  w0_sh[7 * HH + n], base);
                const float wa = w0_sh[n], wb = w0_sh[HH + n];
#pragma unroll 4
                for (int rr = 0; rr < 16; rr++) {
                    const int r = l0r0 + rr;
                    float a = fmaf(st_sh[2 * r], wa, fmaf(st_sh[2 * r + 1], wb, base));
                    a = fmaxf(a, 0.0f);
                    float h = __bfloat162float(__float2bfloat16(a));
                    Ah[r * AS + n] = __float2bfloat16(a);
                    Al[r * AS + n] = __float2bfloat16(a - h);
                }
            }
        }
        __syncthreads();

        // ---- layer 1: split-K GEMM + exchange + bias/relu epilogue -> Bh/Bl
        {
            float D[2][4][4];
            tc_gemm_sk(D, Ah, Al, g_W1, wn, kg, lane);
            float v[4][4];
            exchange_partial(D, pf, wn, kg, lane, v);
            // epilogue: this warp owns m-tile kg (rows 16kg..16kg+16)
#pragma unroll
            for (int nt = 0; nt < 4; nt++) {
                const int col = (4 * wn + nt) * 8 + (lane & 3) * 2;
                const float bb0 = b1_sh[col], bb1 = b1_sh[col + 1];
#pragma unroll
                for (int h = 0; h < 2; h++) {
                    const int row = kg * 16 + rbase + h * 8;
                    float x0 = fmaxf(v[nt][2 * h + 0] + bb0, 0.0f);
                    float x1 = fmaxf(v[nt][2 * h + 1] + bb1, 0.0f);
                    float h0 = __bfloat162float(__float2bfloat16(x0));
                    float h1 = __bfloat162float(__float2bfloat16(x1));
                    *reinterpret_cast<uint32_t*>(Bh + row * AS + col) = bfpack(h0, h1);
                    *reinterpret_cast<uint32_t*>(Bl + row * AS + col) =
                        bfpack(x0 - h0, x1 - h1);
                }
            }
        }
        __syncthreads();

        // ---- layer 2: split-K GEMM + exchange + fused layer 3 in registers.
        // Warp's reduced 4-nt accumulators (cols 32wn..32wn+32, m-tile kg) form
        // TWO m16k16 A-fragments for layer3 k-slices 2wn and 2wn+1.
        {
            float D[2][4][4];
            tc_gemm_sk(D, Bh, Bl, g_W2, wn, kg, lane);
            float v[4][4];
            exchange_partial(D, pf, wn, kg, lane, v);
            float D3[4] = {0.f, 0.f, 0.f, 0.f};
#pragma unroll
            for (int sl = 0; sl < 2; sl++) {       // k-slice = nt pair
                uint32_t ah[4], al[4];
#pragma unroll
                for (int q = 0; q < 2; q++) {      // nt within slice
                    const int nt = sl * 2 + q;
                    const int col = (4 * wn + nt) * 8 + (lane & 3) * 2;
                    const float bb0 = b2_sh[col], bb1 = b2_sh[col + 1];
#pragma unroll
                    for (int h = 0; h < 2; h++) {
                        float x0 = fmaxf(v[nt][2 * h + 0] + bb0, 0.0f);
                        float x1 = fmaxf(v[nt][2 * h + 1] + bb1, 0.0f);
                        float h0 = __bfloat162float(__float2bfloat16(x0));
                        float h1 = __bfloat162float(__float2bfloat16(x1));
                        ah[q * 2 + h] = bfpack(h0, h1);
                        al[q * 2 + h] = bfpack(x0 - h0, x1 - h1);
                    }
                }
                const uint4 w3v = sl ? w3v1 : w3v0;
                mma_bf16(D3, ah, w3v.x, w3v.y);
                mma_bf16(D3, ah, w3v.z, w3v.w);
                mma_bf16(D3, al, w3v.x, w3v.y);
            }
            // dump layer3 partial for m-tile kg: slot (wn*2 + kg)
            reinterpret_cast<float4*>(pf3)[(wn * 2 + kg) * 32 + lane] =
                make_float4(D3[0], D3[1], D3[2], D3[3]);
        }
        __syncthreads();

        // ---- reduce 8 partials per m-tile + SDE sample + global writes
        // value(row lr, col c): lane = (lr&7)*4 + (c>>1), reg = (c&1) + 2*(lr>>3)
        if (tid < M_CTA * 2) {
            const int r = tid >> 1, d = tid & 1, p = row0 + r;
            const int mt = r >> 4, lr = r & 15;
            const int lbase = (lr & 7) * 4;
            const int rhalf = 2 * (lr >> 3);
            float2 e = __ldg(reinterpret_cast<const float2*>(path_seed) + s * PP + p);
            const int mb = PP * 202 + (p * 100 + s) * 2;
            const int sb = PP * 202 + PP * 200 + (p * 100 + s) * 4;
            if (d == 0) {
                float v0 = 0.f, v2 = 0.f;   // cols 0 and 2
#pragma unroll
                for (int w = 0; w < 8; w++) {
                    const float* pw = pf3 + ((w * 2 + mt) * 32) * 4;
                    v0 += pw[(lbase + 0) * 4 + rhalf + 0];
                    v2 += pw[(lbase + 1) * 4 + rhalf + 0];
                }
                float mu0 = v0 + b3_sh[0];
                float s11 = softplusf(v2 + b3_sh[2]);
                float st0 = st_sh[2 * r];
                float n0v = softplusf(st0 + DTC * mu0 + SQRT_DTC * (s11 * e.x));
                st_sh[2 * r] = n0v;
                out[p * 202 + (s + 1)] = n0v;
                if (s == 0) out[p * 202 + 0] = st0;
                out[mb + 0] = mu0;
                out[sb + 0] = s11;
                out[sb + 1] = 0.0f;
            } else {
                float v1 = 0.f, v3 = 0.f, v4 = 0.f;   // cols 1, 3, 4
#pragma unroll
                for (int w = 0; w < 8; w++) {
                    const float* pw = pf3 + ((w * 2 + mt) * 32) * 4;
                    v1 += pw[(lbase + 0) * 4 + rhalf + 1];
                    v3 += pw[(lbase + 1) * 4 + rhalf + 1];
                    v4 += pw[(lbase + 2) * 4 + rhalf + 0];
                }
                float mu1 = v1 + b3_sh[1];
                float s21 = v3 + b3_sh[3];
                float s22 = softplusf(v4 + b3_sh[4]);
                float st1 = st_sh[2 * r + 1];
                float n1v = softplusf(st1 + DTC * mu1 + SQRT_DTC * (s21 * e.x + s22 * e.y));
                st_sh[2 * r + 1] = n1v;
                out[p * 202 + 101 + (s + 1)] = n1v;
                if (s == 0) out[p * 202 + 101] = st1;
                out[mb + 1] = mu1;
                out[sb + 2] = s21;
                out[sb + 3] = s22;
            }
        }
        __syncthreads();
    }
}

extern "C" void kernel_launch(void* const* d_in, const int* in_sizes, int n_in,
                              void* d_out, int out_size) {
    const float* W0 = (const float*)d_in[0];
    const float* b0 = (const float*)d_in[1];
    const float* W1 = (const float*)d_in[2];
    const float* b1 = (const float*)d_in[3];
    const float* W2 = (const float*)d_in[4];
    const float* b2 = (const float*)d_in[5];
    const float* W3 = (const float*)d_in[6];
    const float* b3 = (const float*)d_in[7];
    const float* obs_init = (const float*)d_in[8];
    const float* feature_init = (const float*)d_in[9];
    const float* tn_store = (const float*)d_in[10];
    const float* x1_store = (const float*)d_in[11];
    const float* x2_store = (const float*)d_in[12];
    const float* path_seed = (const float*)d_in[13];
    float* out = (float*)d_out;

    // 1) split weights into hi/lo bf16 fragment arrays (hi+lo packed uint4)
    prep_kernel<<<130, 256>>>(W1, W2, W3);

    // 2) persistent 100-step trajectory kernel
    cudaFuncSetAttribute(lv_tc_kernel, cudaFuncAttributeMaxDynamicSharedMemorySize,
                         SMEM_BYTES);
    lv_tc_kernel<<<NCTA, NTHREADS, SMEM_BYTES>>>(
        W0, b0, b1, b2, b3, obs_init, feature_init,
        tn_store, x1_store, x2_store, path_seed, out);
}

// round 17
// speedup vs baseline: 1.1007x; 1.1007x over previous
#include <cuda_runtime.h>
#include <cuda_bf16.h>
#include <cstdint>

#define PP        4096
#define HH        256
#define NSTEPS    100
#define DTC       0.1f
#define SQRT_DTC  0.31622776601683794f
#define M_CTA     32
#define NCTA      (PP / M_CTA)   // 128
#define NTHREADS  512            // 2 groups x 8 warps; warp: 1 m-tile x 4 n-tiles
#define AS        264            // bf16 row stride (528B): conflict-free ldsm/STS

// smem: 4 act bufs (67584) + w0 (8192) + b0/b1/b2 (3072) + b3 (32) + st (256)
//       + inp0 (1024) + pf3 (8192) = 88352
#define SMEM_BYTES 88352

// Weight fragments, mma.m16n8k16 B-op order, hi+lo packed per uint4:
// [kt][n8][lane] -> {bh0, bh1, bl0, bl1}
__device__ uint4 g_W1[16 * 32 * 32];
__device__ uint4 g_W2[16 * 32 * 32];
__device__ uint4 g_W3[16 * 32];

__device__ __forceinline__ float softplusf(float x) {
    return fmaxf(x, 0.0f) + log1pf(expf(-fabsf(x)));
}
__device__ __forceinline__ uint32_t bfpack(float a, float b) {
    __nv_bfloat162 v = __floats2bfloat162_rn(a, b);   // .x = a (low half)
    return *reinterpret_cast<uint32_t*>(&v);
}
#define GROUP_BAR(g) asm volatile("bar.sync %0, 256;" :: "r"(1 + (g)) : "memory")

// ---------------- prep: fp32 weights -> hi/lo bf16 fragment arrays ----------------
__global__ void prep_kernel(const float* __restrict__ W1,
                            const float* __restrict__ W2,
                            const float* __restrict__ W3) {
    const int idx = blockIdx.x * blockDim.x + threadIdx.x;
    const int TOT = 16 * 32 * 32;
    if (idx < 2 * TOT) {
        const int l = idx / TOT, r = idx % TOT;
        const int kt = r >> 10;
        const int n8 = (r >> 5) & 31;
        const int lane = r & 31;
        const int k0 = kt * 16 + (lane & 3) * 2;
        const int n = n8 * 8 + (lane >> 2);
        const float* W = l ? W2 : W1;
        float x[4];
        x[0] = W[(k0)     * HH + n];
        x[1] = W[(k0 + 1) * HH + n];
        x[2] = W[(k0 + 8) * HH + n];
        x[3] = W[(k0 + 9) * HH + n];
        float h[4], lo[4];
#pragma unroll
        for (int i = 0; i < 4; i++) {
            h[i]  = __bfloat162float(__float2bfloat16(x[i]));
            lo[i] = x[i] - h[i];
        }
        uint4 v;
        v.x = bfpack(h[0], h[1]);   v.y = bfpack(h[2], h[3]);
        v.z = bfpack(lo[0], lo[1]); v.w = bfpack(lo[2], lo[3]);
        if (l) g_W2[r] = v; else g_W1[r] = v;
    } else if (idx < 2 * TOT + 512) {
        const int r = idx - 2 * TOT;
        const int kt = r >> 5, lane = r & 31;
        const int k0 = kt * 16 + (lane & 3) * 2;
        const int n = lane >> 2;
        float x[4] = {0.f, 0.f, 0.f, 0.f};
        if (n < 5) {
            x[0] = W3[(k0)     * 5 + n];
            x[1] = W3[(k0 + 1) * 5 + n];
            x[2] = W3[(k0 + 8) * 5 + n];
            x[3] = W3[(k0 + 9) * 5 + n];
        }
        float h[4], lo[4];
#pragma unroll
        for (int i = 0; i < 4; i++) {
            h[i]  = __bfloat162float(__float2bfloat16(x[i]));
            lo[i] = x[i] - h[i];
        }
        uint4 v;
        v.x = bfpack(h[0], h[1]);   v.y = bfpack(h[2], h[3]);
        v.z = bfpack(lo[0], lo[1]); v.w = bfpack(lo[2], lo[3]);
        g_W3[r] = v;
    }
}

// ---------------- tensor-core primitives ----------------
__device__ __forceinline__ void ldsm4(uint32_t* r, const __nv_bfloat16* p) {
    uint32_t addr = (uint32_t)__cvta_generic_to_shared(p);
    asm volatile("ldmatrix.sync.aligned.m8n8.x4.shared.b16 {%0,%1,%2,%3}, [%4];"
                 : "=r"(r[0]), "=r"(r[1]), "=r"(r[2]), "=r"(r[3]) : "r"(addr));
}
__device__ __forceinline__ void mma_bf16(float* d, const uint32_t* a,
                                         uint32_t b0, uint32_t b1) {
    asm volatile(
        "mma.sync.aligned.m16n8k16.row.col.f32.bf16.bf16.f32 "
        "{%0,%1,%2,%3}, {%4,%5,%6,%7}, {%8,%9}, {%0,%1,%2,%3};"
        : "+f"(d[0]), "+f"(d[1]), "+f"(d[2]), "+f"(d[3])
        : "r"(a[0]), "r"(a[1]), "r"(a[2]), "r"(a[3]), "r"(b0), "r"(b1));
}

struct AF { uint32_t ah[4], al[4]; };   // one m16k16 tile, hi + lo
struct BF { uint4 b[4]; };              // 4 n-tiles: hi in (x,y), lo in (z,w)

__device__ __forceinline__ void load_A1(AF& a, const __nv_bfloat16* Ah,
                                        const __nv_bfloat16* Al, int arow, int co) {
    ldsm4(a.ah, Ah + arow * AS + co);
    ldsm4(a.al, Al + arow * AS + co);
}
__device__ __forceinline__ void load_B4(BF& f, const uint4* __restrict__ bp,
                                        int kt) {
    const uint4* p = bp + kt * 1024;
#pragma unroll
    for (int nt = 0; nt < 4; nt++) f.b[nt] = __ldg(p + nt * 32);
}
__device__ __forceinline__ void mma12(float D[4][4], const AF& a, const BF& f) {
#pragma unroll
    for (int nt = 0; nt < 4; nt++) {
        mma_bf16(D[nt], a.ah, f.b[nt].x, f.b[nt].y);
        mma_bf16(D[nt], a.ah, f.b[nt].z, f.b[nt].w);
        mma_bf16(D[nt], a.al, f.b[nt].x, f.b[nt].y);
    }
}

// Per-group GEMM: warp wn of group g computes rows [16g,16g+16) x cols
// [32wn, 32wn+32) over all 16 k-tiles. A+B double buffered.
__device__ __forceinline__ void tc_gemm_g(
    float D[4][4], const __nv_bfloat16* Ah, const __nv_bfloat16* Al,
    const uint4* __restrict__ B, int wn, int g, int lane) {
#pragma unroll
    for (int nt = 0; nt < 4; nt++)
#pragma unroll
        for (int i = 0; i < 4; i++) D[nt][i] = 0.0f;

    const int arow = 16 * g + (lane & 7) + ((lane >> 3) & 1) * 8;
    const int acol = (lane >> 4) * 8;
    const uint4* bp = B + wn * 128 + lane;   // + kt*1024 + nt*32

    BF B0, B1;
    AF A0, A1;
    load_B4(B0, bp, 0);
    load_B4(B1, bp, 1);
    load_A1(A0, Ah, Al, arow, acol);
#pragma unroll
    for (int i = 0; i < 8; i++) {
        const int kt = 2 * i;
        load_A1(A1, Ah, Al, arow, (kt + 1) * 16 + acol);
        mma12(D, A0, B0);
        if (i < 7) load_B4(B0, bp, kt + 2);
        if (i < 7) load_A1(A0, Ah, Al, arow, (kt + 2) * 16 + acol);
        mma12(D, A1, B1);
        if (i < 7) load_B4(B1, bp, kt + 3);
    }
}

// ---------------- main persistent kernel ----------------
__global__ void __launch_bounds__(NTHREADS, 1) lv_tc_kernel(
    const float* __restrict__ W0, const float* __restrict__ b0,
    const float* __restrict__ b1, const float* __restrict__ b2,
    const float* __restrict__ b3,
    const float* __restrict__ obs_init, const float* __restrict__ feature_init,
    const float* __restrict__ tn_store, const float* __restrict__ x1_store,
    const float* __restrict__ x2_store, const float* __restrict__ path_seed,
    float* __restrict__ out) {
    extern __shared__ __align__(16) unsigned char smem_raw[];
    __nv_bfloat16* Ah = reinterpret_cast<__nv_bfloat16*>(smem_raw);
    __nv_bfloat16* Al = Ah + M_CTA * AS;
    __nv_bfloat16* Bh = Al + M_CTA * AS;
    __nv_bfloat16* Bl = Bh + M_CTA * AS;
    float* w0_sh = reinterpret_cast<float*>(Bl + M_CTA * AS);
    float* b0_sh = w0_sh + 8 * HH;
    float* b1_sh = b0_sh + HH;
    float* b2_sh = b1_sh + HH;
    float* b3_sh = b2_sh + HH;       // 8
    float* st_sh = b3_sh + 8;        // 64
    float* inp0  = st_sh + 64;       // 32*8
    float* pf3   = inp0 + M_CTA * 8; // 16 slots * 32 lanes * 4 = 2048 f

    const int tid = threadIdx.x;
    const int warp = tid >> 5, lane = tid & 31;
    const int g = warp >> 3;          // group 0/1: particles [16g, 16g+16)
    const int wn = warp & 7;          // n-group within the group's GEMM
    const int tid_g = tid & 255;
    const int row0 = blockIdx.x * M_CTA;

    // one-time staging
    for (int i = tid; i < 8 * HH; i += NTHREADS) w0_sh[i] = W0[i];
    if (tid < HH) { b0_sh[tid] = b0[tid]; b1_sh[tid] = b1[tid]; b2_sh[tid] = b2[tid]; }
    if (tid < 8) b3_sh[tid] = (tid < 5) ? b3[tid] : 0.0f;
    if (tid < M_CTA * 2) st_sh[tid] = obs_init[row0 * 2 + tid];
    if (tid < M_CTA * 8) {
        int r = tid >> 3, k = tid & 7;
        inp0[tid] = (k < 2) ? obs_init[(row0 + r) * 2 + k]
                            : feature_init[(row0 + r) * 6 + (k - 2)];
    }
    // layer-3 B fragments for this warp's two k-slices (constant -> registers)
    const uint4 w3v0 = __ldg(&g_W3[(2 * wn)     * 32 + lane]);
    const uint4 w3v1 = __ldg(&g_W3[(2 * wn + 1) * 32 + lane]);
    float t_reg = __ldg(feature_init);   // t0 = feature_init[0,0,0]
    __syncthreads();

    // layer-0: each group thread owns col n = tid_g for its group's 16 rows
    const int l0n = tid_g;
    const int rbase = lane >> 2;

#pragma unroll 1
    for (int s = 0; s < NSTEPS; s++) {
        // ---- layer 0 (scalar fp32) -> Ah/Al rows [16g, 16g+16)
        {
            const int n = l0n;
            if (s == 0) {
#pragma unroll 4
                for (int rr = 0; rr < 16; rr++) {
                    const int r = 16 * g + rr;
                    float a = b0_sh[n];
#pragma unroll
                    for (int k = 0; k < 8; k++)
                        a = fmaf(inp0[r * 8 + k], w0_sh[k * HH + n], a);
                    a = fmaxf(a, 0.0f);
                    float h = __bfloat162float(__float2bfloat16(a));
                    Ah[r * AS + n] = __float2bfloat16(a);
                    Al[r * AS + n] = __float2bfloat16(a - h);
                }
            } else {
                t_reg += DTC;   // exact sequential fp32 time accumulation
                const int i = s - 1;
                const float f_tn = __ldg(tn_store + i);
                const float f_x1 = __ldg(x1_store + i);
                const float f_x2 = __ldg(x2_store + i);
                float base = b0_sh[n];
                base = fmaf(t_reg, w0_sh[2 * HH + n], base);
                base = fmaf(f_tn,  w0_sh[3 * HH + n], base);
                base = fmaf(f_x1,  w0_sh[4 * HH + n], base);
                base = fmaf(f_x2,  w0_sh[5 * HH + n], base);
                base = fmaf(f_x1,  w0_sh[6 * HH + n], base);
                base = fmaf(f_x2,  w0_sh[7 * HH + n], base);
                const float wa = w0_sh[n], wb = w0_sh[HH + n];
#pragma unroll 4
                for (int rr = 0; rr < 16; rr++) {
                    const int r = 16 * g + rr;
                    float a = fmaf(st_sh[2 * r], wa, fmaf(st_sh[2 * r + 1], wb, base));
                    a = fmaxf(a, 0.0f);
                    float h = __bfloat162float(__float2bfloat16(a));
                    Ah[r * AS + n] = __float2bfloat16(a);
                    Al[r * AS + n] = __float2bfloat16(a - h);
                }
            }
        }
        GROUP_BAR(g);

        // ---- layer 1 GEMM + bias/relu -> Bh/Bl (rows 16g..16g+16)
        {
            float D[4][4];
            tc_gemm_g(D, Ah, Al, g_W1, wn, g, lane);
#pragma unroll
            for (int nt = 0; nt < 4; nt++) {
                const int col = (4 * wn + nt) * 8 + (lane & 3) * 2;
                const float bb0 = b1_sh[col], bb1 = b1_sh[col + 1];
#pragma unroll
                for (int h = 0; h < 2; h++) {
                    const int row = 16 * g + rbase + h * 8;
                    float x0 = fmaxf(D[nt][2 * h + 0] + bb0, 0.0f);
                    float x1 = fmaxf(D[nt][2 * h + 1] + bb1, 0.0f);
                    float h0 = __bfloat162float(__float2bfloat16(x0));
                    float h1 = __bfloat162float(__float2bfloat16(x1));
                    *reinterpret_cast<uint32_t*>(Bh + row * AS + col) = bfpack(h0, h1);
                    *reinterpret_cast<uint32_t*>(Bl + row * AS + col) =
                        bfpack(x0 - h0, x1 - h1);
                }
            }
        }
        GROUP_BAR(g);

        // ---- layer 2 GEMM + bias/relu + fused layer 3 in registers.
        // Warp's 4-nt accumulators (cols 32wn..32wn+32) form TWO m16k16
        // A-fragments for layer3 k-slices 2wn and 2wn+1.
        {
            float D[4][4];
            tc_gemm_g(D, Bh, Bl, g_W2, wn, g, lane);
            float D3[4] = {0.f, 0.f, 0.f, 0.f};
#pragma unroll
            for (int sl = 0; sl < 2; sl++) {
                uint32_t ah[4], al[4];
#pragma unroll
                for (int q = 0; q < 2; q++) {
                    const int nt = sl * 2 + q;
                    const int col = (4 * wn + nt) * 8 + (lane & 3) * 2;
                    const float bb0 = b2_sh[col], bb1 = b2_sh[col + 1];
#pragma unroll
                    for (int h = 0; h < 2; h++) {
                        float x0 = fmaxf(D[nt][2 * h + 0] + bb0, 0.0f);
                        float x1 = fmaxf(D[nt][2 * h + 1] + bb1, 0.0f);
                        float h0 = __bfloat162float(__float2bfloat16(x0));
                        float h1 = __bfloat162float(__float2bfloat16(x1));
                        ah[q * 2 + h] = bfpack(h0, h1);
                        al[q * 2 + h] = bfpack(x0 - h0, x1 - h1);
                    }
                }
                const uint4 w3v = sl ? w3v1 : w3v0;
                mma_bf16(D3, ah, w3v.x, w3v.y);
                mma_bf16(D3, ah, w3v.z, w3v.w);
                mma_bf16(D3, al, w3v.x, w3v.y);
            }
            reinterpret_cast<float4*>(pf3)[(g * 8 + wn) * 32 + lane] =
                make_float4(D3[0], D3[1], D3[2], D3[3]);
        }
        GROUP_BAR(g);

        // ---- reduce 8 partials + SDE sample + global writes (fp32 exact)
        // value(row lr, col c): lane = (lr&7)*4 + (c>>1), reg = (c&1) + 2*(lr>>3)
        if (tid_g < 32) {
            const int lr = tid_g >> 1, d = tid_g & 1;
            const int r = 16 * g + lr, p = row0 + r;
            const int lbase = (lr & 7) * 4;
            const int rhalf = 2 * (lr >> 3);
            float2 e = __ldg(reinterpret_cast<const float2*>(path_seed) + s * PP + p);
            const int mb = PP * 202 + (p * 100 + s) * 2;
            const int sb = PP * 202 + PP * 200 + (p * 100 + s) * 4;
            if (d == 0) {
                float v0 = 0.f, v2 = 0.f;   // cols 0 and 2
#pragma unroll
                for (int w = 0; w < 8; w++) {
                    const float* pw = pf3 + ((g * 8 + w) * 32) * 4;
                    v0 += pw[(lbase + 0) * 4 + rhalf + 0];
                    v2 += pw[(lbase + 1) * 4 + rhalf + 0];
                }
                float mu0 = v0 + b3_sh[0];
                float s11 = softplusf(v2 + b3_sh[2]);
                float st0 = st_sh[2 * r];
                float n0v = softplusf(st0 + DTC * mu0 + SQRT_DTC * (s11 * e.x));
                st_sh[2 * r] = n0v;
                out[p * 202 + (s + 1)] = n0v;
                if (s == 0) out[p * 202 + 0] = st0;
                out[mb + 0] = mu0;
                out[sb + 0] = s11;
                out[sb + 1] = 0.0f;
            } else {
                float v1 = 0.f, v3 = 0.f, v4 = 0.f;   // cols 1, 3, 4
#pragma unroll
                for (int w = 0; w < 8; w++) {
                    const float* pw = pf3 + ((g * 8 + w) * 32) * 4;
                    v1 += pw[(lbase + 0) * 4 + rhalf + 1];
                    v3 += pw[(lbase + 1) * 4 + rhalf + 1];
                    v4 += pw[(lbase + 2) * 4 + rhalf + 0];
                }
                float mu1 = v1 + b3_sh[1];
                float s21 = v3 + b3_sh[3];
                float s22 = softplusf(v4 + b3_sh[4]);
                float st1 = st_sh[2 * r + 1];
                float n1v = softplusf(st1 + DTC * mu1 + SQRT_DTC * (s21 * e.x + s22 * e.y));
                st_sh[2 * r + 1] = n1v;
                out[p * 202 + 101 + (s + 1)] = n1v;
                if (s == 0) out[p * 202 + 101] = st1;
                out[mb + 1] = mu1;
                out[sb + 2] = s21;
                out[sb + 3] = s22;
            }
        }
        GROUP_BAR(g);
    }
}

extern "C" void kernel_launch(void* const* d_in, const int* in_sizes, int n_in,
                              void* d_out, int out_size) {
    const float* W0 = (const float*)d_in[0];
    const float* b0 = (const float*)d_in[1];
    const float* W1 = (const float*)d_in[2];
    const float* b1 = (const float*)d_in[3];
    const float* W2 = (const float*)d_in[4];
    const float* b2 = (const float*)d_in[5];
    const float* W3 = (const float*)d_in[6];
    const float* b3 = (const float*)d_in[7];
    const float* obs_init = (const float*)d_in[8];
    const float* feature_init = (const float*)d_in[9];
    const float* tn_store = (const float*)d_in[10];
    const float* x1_store = (const float*)d_in[11];
    const float* x2_store = (const float*)d_in[12];
    const float* path_seed = (const float*)d_in[13];
    float* out = (float*)d_out;

    // 1) split weights into hi/lo bf16 fragment arrays (hi+lo packed uint4)
    prep_kernel<<<130, 256>>>(W1, W2, W3);

    // 2) persistent 100-step trajectory kernel
    cudaFuncSetAttribute(lv_tc_kernel, cudaFuncAttributeMaxDynamicSharedMemorySize,
                         SMEM_BYTES);
    lv_tc_kernel<<<NCTA, NTHREADS, SMEM_BYTES>>>(
        W0, b0, b1, b2, b3, obs_init, feature_init,
        tn_store, x1_store, x2_store, path_seed, out);
}